// round 4
// baseline (speedup 1.0000x reference)
#include <cuda_runtime.h>

#define NROWS 8192
#define D 128
#define MARGIN 0.3f
#define BM 64
#define BN 64
#define BK 32
#define NSPLIT 4

__device__ float    g_sq[NROWS];
__device__ int      g_lab[NROWS];
__device__ unsigned g_ap[NROWS];   // float bits of running max positive dist (dist >= 0: uint order == float order)
__device__ unsigned g_an[NROWS];   // float bits of running min negative dist

// ---------------------------------------------------------------------------
// Kernel A0: normalize labels (runtime int32-vs-int64 probe) + init mining bufs
// ---------------------------------------------------------------------------
__global__ void label_kernel(const void* __restrict__ Traw) {
    // probe: if targets were truly int64, first 16 int64 values are all in [0,512)
    const long long* t64 = (const long long*)Traw;
    bool is64 = true;
    #pragma unroll
    for (int i = 0; i < 16; i++) {
        long long v = t64[i];
        if (v < 0 || v >= 512) is64 = false;
    }
    const int* t32 = (const int*)Traw;
    int i = blockIdx.x * blockDim.x + threadIdx.x;
    if (i < NROWS) {
        g_lab[i] = is64 ? (int)t64[i] : t32[i];
        g_ap[i]  = 0u;            // 0.0f
        g_an[i]  = 0x7F800000u;   // +inf
    }
}

// ---------------------------------------------------------------------------
// Kernel A1: row squared norms (one warp per row, lane loads float4)
// ---------------------------------------------------------------------------
__global__ void prep_kernel(const float* __restrict__ X) {
    int warp = (blockIdx.x * blockDim.x + threadIdx.x) >> 5;
    int lane = threadIdx.x & 31;
    if (warp >= NROWS) return;
    float4 v = reinterpret_cast<const float4*>(X + (size_t)warp * D)[lane];
    float s = v.x * v.x + v.y * v.y + v.z * v.z + v.w * v.w;
    #pragma unroll
    for (int o = 16; o; o >>= 1) s += __shfl_xor_sync(0xffffffff, s, o);
    if (lane == 0) g_sq[warp] = s;
}

// ---------------------------------------------------------------------------
// Kernel B: fused tiled GEMM + distance + batch-hard mining
// CTA: rows [m0, m0+64), columns [c0, c0+2048)   grid = (128, 4)
// blockDim (16,16); each thread owns a 4x4 micro-tile
// ---------------------------------------------------------------------------
__global__ __launch_bounds__(256) void tile_kernel(const float* __restrict__ X) {
    __shared__ float As[BK][BM + 4];   // [k][m]
    __shared__ float Bs[BK][BN + 4];

    const int tx  = threadIdx.x;
    const int ty  = threadIdx.y;
    const int tid = ty * 16 + tx;

    const int m0 = blockIdx.x * BM;
    const int c0 = blockIdx.y * (NROWS / NSPLIT);
    const int c1 = c0 + NROWS / NSPLIT;

    int   trow[4];
    float sqrow[4];
    #pragma unroll
    for (int i = 0; i < 4; i++) {
        int r = m0 + ty * 4 + i;
        trow[i]  = g_lab[r];
        sqrow[i] = g_sq[r];
    }

    float maxp[4] = {0.f, 0.f, 0.f, 0.f};
    float minn[4];
    #pragma unroll
    for (int i = 0; i < 4; i++) minn[i] = __int_as_float(0x7f800000);

    for (int n0 = c0; n0 < c1; n0 += BN) {
        float acc[4][4];
        #pragma unroll
        for (int i = 0; i < 4; i++)
            #pragma unroll
            for (int j = 0; j < 4; j++) acc[i][j] = 0.f;

        #pragma unroll
        for (int kk = 0; kk < D; kk += BK) {
            #pragma unroll
            for (int it = 0; it < 2; it++) {
                int idx = tid + it * 256;
                int r = idx >> 3;
                int c = (idx & 7) * 4;
                float4 va = *reinterpret_cast<const float4*>(X + (size_t)(m0 + r) * D + kk + c);
                As[c + 0][r] = va.x; As[c + 1][r] = va.y;
                As[c + 2][r] = va.z; As[c + 3][r] = va.w;
                float4 vb = *reinterpret_cast<const float4*>(X + (size_t)(n0 + r) * D + kk + c);
                Bs[c + 0][r] = vb.x; Bs[c + 1][r] = vb.y;
                Bs[c + 2][r] = vb.z; Bs[c + 3][r] = vb.w;
            }
            __syncthreads();

            #pragma unroll
            for (int k = 0; k < BK; k++) {
                float4 a = *reinterpret_cast<const float4*>(&As[k][ty * 4]);
                float4 b = *reinterpret_cast<const float4*>(&Bs[k][tx * 4]);
                float av[4] = {a.x, a.y, a.z, a.w};
                float bv[4] = {b.x, b.y, b.z, b.w};
                #pragma unroll
                for (int i = 0; i < 4; i++)
                    #pragma unroll
                    for (int j = 0; j < 4; j++)
                        acc[i][j] = fmaf(av[i], bv[j], acc[i][j]);
            }
            __syncthreads();
        }

        // epilogue: distance + mining, fused (no NxN materialization)
        #pragma unroll
        for (int j = 0; j < 4; j++) {
            int   c   = n0 + tx * 4 + j;
            int   tc  = g_lab[c];
            float sqc = g_sq[c];
            #pragma unroll
            for (int i = 0; i < 4; i++) {
                float d2 = sqrow[i] + sqc - 2.f * acc[i][j];
                float d  = sqrtf(fmaxf(d2, 1e-12f));
                if (trow[i] == tc) maxp[i] = fmaxf(maxp[i], d);
                else               minn[i] = fminf(minn[i], d);
            }
        }
    }

    // reduce across the 16 tx lanes that share each row
    #pragma unroll
    for (int i = 0; i < 4; i++) {
        float mp = maxp[i], mn = minn[i];
        #pragma unroll
        for (int o = 8; o; o >>= 1) {
            mp = fmaxf(mp, __shfl_xor_sync(0xffffffff, mp, o));
            mn = fminf(mn, __shfl_xor_sync(0xffffffff, mn, o));
        }
        if (tx == 0) {
            int r = m0 + ty * 4 + i;
            atomicMax(&g_ap[r], __float_as_uint(mp));
            atomicMin(&g_an[r], __float_as_uint(mn));
        }
    }
}

// ---------------------------------------------------------------------------
// Kernel C: final loss + precision reduction
// ---------------------------------------------------------------------------
__global__ void finalize_kernel(float* __restrict__ out, int out_size) {
    __shared__ float sl[256];
    __shared__ float sp[256];
    float loss = 0.f, prec = 0.f;
    for (int i = threadIdx.x; i < NROWS; i += 256) {
        float ap = __uint_as_float(g_ap[i]);
        float an = __uint_as_float(g_an[i]);
        loss += fmaxf(0.f, MARGIN - (an - ap));
        prec += (an > ap) ? 1.f : 0.f;
    }
    sl[threadIdx.x] = loss;
    sp[threadIdx.x] = prec;
    __syncthreads();
    for (int s = 128; s; s >>= 1) {
        if (threadIdx.x < s) {
            sl[threadIdx.x] += sl[threadIdx.x + s];
            sp[threadIdx.x] += sp[threadIdx.x + s];
        }
        __syncthreads();
    }
    if (threadIdx.x == 0) {
        out[0] = sl[0] / (float)NROWS;
        if (out_size > 1) out[1] = sp[0] / (float)NROWS;
    }
}

extern "C" void kernel_launch(void* const* d_in, const int* in_sizes, int n_in,
                              void* d_out, int out_size) {
    const float* X = (const float*)d_in[0];

    label_kernel<<<NROWS / 256, 256>>>(d_in[1]);
    prep_kernel<<<NROWS / 8, 256>>>(X);

    dim3 grid(NROWS / BM, NSPLIT);
    dim3 blk(16, 16);
    tile_kernel<<<grid, blk>>>(X);

    finalize_kernel<<<1, 256>>>((float*)d_out, out_size);
}

// round 8
// speedup vs baseline: 3.4699x; 3.4699x over previous
#include <cuda_runtime.h>
#include <cuda_bf16.h>
#include <cstdint>

#define NR 8192
#define MARGIN 0.3f

// split-bf16 of X: per row 256 bf16 = [hi(0:128) | lo(128:256)]
__device__ __align__(1024) __nv_bfloat16 g_xs[NR * 256];
__device__ float    g_sq[NR];
__device__ int      g_lab[NR];
__device__ unsigned g_ap[NR];   // float bits of running max positive d^2 (>=1e-12 so uint order == float order)
__device__ unsigned g_an[NR];   // float bits of running min negative d^2

__device__ __forceinline__ uint32_t smem_u32(const void* p) {
    uint32_t a;
    asm("{ .reg .u64 t; cvta.to.shared.u64 t, %1; cvt.u32.u64 %0, t; }" : "=r"(a) : "l"(p));
    return a;
}

#define LDSM4(r, addr) \
    asm volatile("ldmatrix.sync.aligned.m8n8.x4.shared.b16 {%0,%1,%2,%3}, [%4];" \
                 : "=r"((r)[0]), "=r"((r)[1]), "=r"((r)[2]), "=r"((r)[3]) : "r"(addr))

#define MMA16816(acc, a, b0v, b1v) \
    asm volatile("mma.sync.aligned.m16n8k16.row.col.f32.bf16.bf16.f32 " \
                 "{%0,%1,%2,%3},{%4,%5,%6,%7},{%8,%9},{%0,%1,%2,%3};" \
                 : "+f"((acc)[0]), "+f"((acc)[1]), "+f"((acc)[2]), "+f"((acc)[3]) \
                 : "r"((a)[0]), "r"((a)[1]), "r"((a)[2]), "r"((a)[3]), "r"(b0v), "r"(b1v))

// smem tile: 128 rows x 264 halves (256 data + 8 pad) = 528 B/row
#define RSTR 528
#define SM_A   0
#define SM_B   (128 * RSTR)
#define SM_SQ  (2 * 128 * RSTR)
#define SM_LAB (SM_SQ + 512)
#define SM_TOTAL (SM_LAB + 512)

// ---------------------------------------------------------------------------
// Kernel A0: normalize labels (runtime int32-vs-int64 probe) + init mining bufs
// ---------------------------------------------------------------------------
__global__ void label_kernel(const void* __restrict__ Traw) {
    const long long* t64 = (const long long*)Traw;
    bool is64 = true;
    #pragma unroll
    for (int i = 0; i < 16; i++) {
        long long v = t64[i];
        if (v < 0 || v >= 512) is64 = false;
    }
    const int* t32 = (const int*)Traw;
    int i = blockIdx.x * blockDim.x + threadIdx.x;
    if (i < NR) {
        g_lab[i] = is64 ? (int)t64[i] : t32[i];
        g_ap[i]  = 0u;
        g_an[i]  = 0x7F800000u;
    }
}

// ---------------------------------------------------------------------------
// Kernel A1: split fp32 -> (hi,lo) bf16 + row squared norms. One warp per row.
// ---------------------------------------------------------------------------
__global__ void prep_kernel(const float* __restrict__ X) {
    int warp = (blockIdx.x * blockDim.x + threadIdx.x) >> 5;
    int lane = threadIdx.x & 31;
    if (warp >= NR) return;
    float4 v = reinterpret_cast<const float4*>(X + (size_t)warp * 128)[lane];
    float s = v.x * v.x + v.y * v.y + v.z * v.z + v.w * v.w;

    __nv_bfloat16 h0 = __float2bfloat16(v.x);
    __nv_bfloat16 h1 = __float2bfloat16(v.y);
    __nv_bfloat16 h2 = __float2bfloat16(v.z);
    __nv_bfloat16 h3 = __float2bfloat16(v.w);
    __nv_bfloat16 l0 = __float2bfloat16(v.x - __bfloat162float(h0));
    __nv_bfloat16 l1 = __float2bfloat16(v.y - __bfloat162float(h1));
    __nv_bfloat16 l2 = __float2bfloat16(v.z - __bfloat162float(h2));
    __nv_bfloat16 l3 = __float2bfloat16(v.w - __bfloat162float(h3));

    __nv_bfloat162* dh = reinterpret_cast<__nv_bfloat162*>(g_xs + (size_t)warp * 256 + lane * 4);
    dh[0] = __halves2bfloat162(h0, h1);
    dh[1] = __halves2bfloat162(h2, h3);
    __nv_bfloat162* dl = reinterpret_cast<__nv_bfloat162*>(g_xs + (size_t)warp * 256 + 128 + lane * 4);
    dl[0] = __halves2bfloat162(l0, l1);
    dl[1] = __halves2bfloat162(l2, l3);

    #pragma unroll
    for (int o = 16; o; o >>= 1) s += __shfl_xor_sync(0xffffffff, s, o);
    if (lane == 0) g_sq[warp] = s;
}

// ---------------------------------------------------------------------------
// Kernel B: mma.sync (HMMA bf16) fused distance + batch-hard mining.
// grid (64, 8): CTA = rows [m0,m0+128) x 8 column tiles of 128.
// 8 warps; warp tile 64x32. dot = Ah*Bh + Al*Bh + Ah*Bl.
// ---------------------------------------------------------------------------
__global__ __launch_bounds__(256, 1) void tile_kernel() {
    extern __shared__ char smem[];
    const uint32_t sb  = smem_u32(smem);
    const int tid = threadIdx.x;
    const int wid = tid >> 5, lane = tid & 31;
    const int m0  = blockIdx.x * 128;
    const int ng0 = blockIdx.y * 8;

    const int m0w = (wid & 1) * 64;    // warp M offset in tile
    const int n0w = (wid >> 1) * 32;   // warp N offset in tile

    // copy A tile (this CTA's 128 rows, hi|lo = 512B/row) into smem rows of 528B
    {
        const uint4* src = reinterpret_cast<const uint4*>(g_xs) + (size_t)m0 * 32;
        #pragma unroll
        for (int it = 0; it < 16; it++) {
            int idx = it * 256 + tid;
            int r = idx >> 5, q = idx & 31;
            *reinterpret_cast<uint4*>(smem + SM_A + r * RSTR + q * 16) = src[idx];
        }
    }

    // per-thread row metadata: 8 rows = 4 mi-frags x 2 halves
    float sqR[8];
    int   labR[8];
    #pragma unroll
    for (int mi = 0; mi < 4; mi++)
        #pragma unroll
        for (int h = 0; h < 2; h++) {
            int r = m0 + m0w + mi * 16 + (lane >> 2) + h * 8;
            sqR[mi * 2 + h]  = g_sq[r];
            labR[mi * 2 + h] = g_lab[r];
        }

    // ldmatrix base addresses (row & k-sub components fixed per thread)
    uint32_t aBase[4];
    {
        int rA = ((lane >> 3) & 1) * 8 + (lane & 7);
        int kA = ((lane >> 4) & 1) * 8;   // halves
        #pragma unroll
        for (int mi = 0; mi < 4; mi++)
            aBase[mi] = sb + SM_A + (m0w + mi * 16 + rA) * RSTR + kA * 2;
    }
    uint32_t bBase[2];
    {
        int rB = ((lane >> 4) & 1) * 8 + (lane & 7);
        int kB = ((lane >> 3) & 1) * 8;
        #pragma unroll
        for (int g = 0; g < 2; g++)
            bBase[g] = sb + SM_B + (n0w + g * 16 + rB) * RSTR + kB * 2;
    }

    float maxp[8], minn[8];
    #pragma unroll
    for (int i = 0; i < 8; i++) {
        maxp[i] = __int_as_float(0xff800000);
        minn[i] = __int_as_float(0x7f800000);
    }

    for (int t = 0; t < 8; t++) {
        const int n0 = (ng0 + t) * 128;

        __syncthreads();   // prior epilogue / A-copy done before B overwrite
        {
            const uint4* src = reinterpret_cast<const uint4*>(g_xs) + (size_t)n0 * 32;
            #pragma unroll
            for (int it = 0; it < 16; it++) {
                int idx = it * 256 + tid;
                int r = idx >> 5, q = idx & 31;
                *reinterpret_cast<uint4*>(smem + SM_B + r * RSTR + q * 16) = src[idx];
            }
            if (tid < 128) {
                *reinterpret_cast<float*>(smem + SM_SQ + tid * 4) = g_sq[n0 + tid];
                *reinterpret_cast<int*>(smem + SM_LAB + tid * 4)  = g_lab[n0 + tid];
            }
        }
        __syncthreads();

        float acc[4][4][4];   // [mi][ni][frag]
        #pragma unroll
        for (int mi = 0; mi < 4; mi++)
            #pragma unroll
            for (int ni = 0; ni < 4; ni++)
                #pragma unroll
                for (int e = 0; e < 4; e++) acc[mi][ni][e] = 0.f;

        #pragma unroll
        for (int ks = 0; ks < 8; ks++) {
            const int kh = ks * 16;           // k offset in halves (within 128)
            uint32_t Ah[4][4], Al[4][4], Bh[2][4], Bl[2][4];
            #pragma unroll
            for (int mi = 0; mi < 4; mi++) {
                LDSM4(Ah[mi], aBase[mi] + kh * 2);
                LDSM4(Al[mi], aBase[mi] + (128 + kh) * 2);
            }
            #pragma unroll
            for (int g = 0; g < 2; g++) {
                LDSM4(Bh[g], bBase[g] + kh * 2);
                LDSM4(Bl[g], bBase[g] + (128 + kh) * 2);
            }
            #pragma unroll
            for (int mi = 0; mi < 4; mi++)
                #pragma unroll
                for (int g = 0; g < 2; g++) {
                    // term1: Ah*Bh   term2: Al*Bh   term3: Ah*Bl
                    MMA16816(acc[mi][g * 2 + 0], Ah[mi], Bh[g][0], Bh[g][1]);
                    MMA16816(acc[mi][g * 2 + 1], Ah[mi], Bh[g][2], Bh[g][3]);
                    MMA16816(acc[mi][g * 2 + 0], Al[mi], Bh[g][0], Bh[g][1]);
                    MMA16816(acc[mi][g * 2 + 1], Al[mi], Bh[g][2], Bh[g][3]);
                    MMA16816(acc[mi][g * 2 + 0], Ah[mi], Bl[g][0], Bl[g][1]);
                    MMA16816(acc[mi][g * 2 + 1], Ah[mi], Bl[g][2], Bl[g][3]);
                }
        }

        // epilogue: v = sqc - 2*dot ; mine per row-slot
        const float* ssq  = reinterpret_cast<const float*>(smem + SM_SQ);
        const int*   slab = reinterpret_cast<const int*>(smem + SM_LAB);
        #pragma unroll
        for (int ni = 0; ni < 4; ni++) {
            int   c0 = n0w + ni * 8 + (lane & 3) * 2;
            float sq0 = ssq[c0],  sq1 = ssq[c0 + 1];
            int   lb0 = slab[c0], lb1 = slab[c0 + 1];
            #pragma unroll
            for (int mi = 0; mi < 4; mi++) {
                #pragma unroll
                for (int h = 0; h < 2; h++) {
                    int s = mi * 2 + h;
                    float v0 = fmaf(-2.f, acc[mi][ni][h * 2 + 0], sq0);
                    float v1 = fmaf(-2.f, acc[mi][ni][h * 2 + 1], sq1);
                    if (lb0 == labR[s]) maxp[s] = fmaxf(maxp[s], v0);
                    else                minn[s] = fminf(minn[s], v0);
                    if (lb1 == labR[s]) maxp[s] = fmaxf(maxp[s], v1);
                    else                minn[s] = fminf(minn[s], v1);
                }
            }
        }
    }

    // reduce over the 4 lanes of each quad (same row set), then atomics
    #pragma unroll
    for (int s = 0; s < 8; s++) {
        float mp = maxp[s], mn = minn[s];
        mp = fmaxf(mp, __shfl_xor_sync(0xffffffff, mp, 1));
        mp = fmaxf(mp, __shfl_xor_sync(0xffffffff, mp, 2));
        mn = fminf(mn, __shfl_xor_sync(0xffffffff, mn, 1));
        mn = fminf(mn, __shfl_xor_sync(0xffffffff, mn, 2));
        if ((lane & 3) == 0) {
            int mi = s >> 1, h = s & 1;
            int r = m0 + m0w + mi * 16 + (lane >> 2) + h * 8;
            float apv = fmaxf(mp + sqR[s], 1e-12f);
            float anv = fmaxf(mn + sqR[s], 1e-12f);
            atomicMax(&g_ap[r], __float_as_uint(apv));
            atomicMin(&g_an[r], __float_as_uint(anv));
        }
    }
}

// ---------------------------------------------------------------------------
// Kernel C: final loss + precision (sqrt on 2*8192 values only)
// ---------------------------------------------------------------------------
__global__ void finalize_kernel(float* __restrict__ out, int out_size) {
    __shared__ float sl[256];
    __shared__ float sp[256];
    float loss = 0.f, prec = 0.f;
    for (int i = threadIdx.x; i < NR; i += 256) {
        float ap = sqrtf(fmaxf(__uint_as_float(g_ap[i]), 1e-12f));
        float an = sqrtf(fmaxf(__uint_as_float(g_an[i]), 1e-12f));
        loss += fmaxf(0.f, MARGIN - (an - ap));
        prec += (an > ap) ? 1.f : 0.f;
    }
    sl[threadIdx.x] = loss;
    sp[threadIdx.x] = prec;
    __syncthreads();
    for (int s = 128; s; s >>= 1) {
        if (threadIdx.x < s) {
            sl[threadIdx.x] += sl[threadIdx.x + s];
            sp[threadIdx.x] += sp[threadIdx.x + s];
        }
        __syncthreads();
    }
    if (threadIdx.x == 0) {
        out[0] = sl[0] / (float)NR;
        if (out_size > 1) out[1] = sp[0] / (float)NR;
    }
}

extern "C" void kernel_launch(void* const* d_in, const int* in_sizes, int n_in,
                              void* d_out, int out_size) {
    const float* X = (const float*)d_in[0];

    cudaFuncSetAttribute(tile_kernel, cudaFuncAttributeMaxDynamicSharedMemorySize, SM_TOTAL);

    label_kernel<<<NR / 256, 256>>>(d_in[1]);
    prep_kernel<<<NR / 8, 256>>>(X);

    dim3 grid(64, 8);
    tile_kernel<<<grid, 256, SM_TOTAL>>>();

    finalize_kernel<<<1, 256>>>((float*)d_out, out_size);
}